// round 1
// baseline (speedup 1.0000x reference)
#include <cuda_runtime.h>
#include <math.h>

#define EMBED 1024
#define DFF   4096
#define BATCH 4
#define SEQ   2048
#define TOK   (BATCH * SEQ)   // 8192

// ---------------- scratch (static device allocations; allowed) ----------------
__device__ float g_Q [TOK * EMBED];
__device__ float g_K [TOK * EMBED];
__device__ float g_V [TOK * EMBED];
__device__ float g_SC[BATCH * SEQ * SEQ];
__device__ float g_A [TOK * EMBED];
__device__ float g_P1[TOK * EMBED];
__device__ float g_X [TOK * EMBED];
__device__ float g_H [TOK * DFF];
__device__ float g_P2[TOK * EMBED];

// ---------------------------------------------------------------------------
// Tiled fp32 GEMM: C[M,N] = A[M,K] @ B(+epilogue)
//   TB=false: B is [K,N] row-major (NN)
//   TB=true : B is [N,K] row-major, compute A @ B^T (NT)
// Block tile 128x128, K-tile 16, 256 threads, 8x8 per-thread microtile.
// All shapes used are exact multiples of tiles -> no bounds checks.
// Batched over blockIdx.z with element strides sA/sB/sC (residual uses sC).
// ---------------------------------------------------------------------------
template<bool TB, bool BIAS, bool RELU, bool RES>
__global__ void __launch_bounds__(256) gemm_k(
    const float* __restrict__ A, const float* __restrict__ Bm,
    const float* __restrict__ bias, const float* __restrict__ Res,
    float* __restrict__ C,
    int M, int N, int K,
    size_t sA, size_t sB, size_t sC)
{
    __shared__ float As[16][128];
    __shared__ float Bs[16][128];

    const int tid = threadIdx.x;
    const int tx  = tid & 15;
    const int ty  = tid >> 4;
    const int bx  = blockIdx.x;
    const int by  = blockIdx.y;
    const int bz  = blockIdx.z;

    const float* Ab = A  + (size_t)bz * sA;
    const float* Bb = Bm + (size_t)bz * sB;
    float*       Cb = C  + (size_t)bz * sC;

    const int rowBase = by * 128;
    const int colBase = bx * 128;

    float acc[8][8];
    #pragma unroll
    for (int i = 0; i < 8; i++)
        #pragma unroll
        for (int j = 0; j < 8; j++)
            acc[i][j] = 0.0f;

    for (int k0 = 0; k0 < K; k0 += 16) {
        // ---- load A tile (transpose into As[k][m]) ----
        #pragma unroll
        for (int i = 0; i < 2; i++) {
            int ld = tid + i * 256;          // 0..511
            int r  = ld >> 2;                // 0..127
            int c  = (ld & 3) << 2;          // 0,4,8,12
            float4 v = *reinterpret_cast<const float4*>(
                &Ab[(size_t)(rowBase + r) * K + k0 + c]);
            As[c + 0][r] = v.x; As[c + 1][r] = v.y;
            As[c + 2][r] = v.z; As[c + 3][r] = v.w;
        }
        // ---- load B tile into Bs[k][n] ----
        if (TB) {
            #pragma unroll
            for (int i = 0; i < 2; i++) {
                int ld = tid + i * 256;
                int r  = ld >> 2;            // n index 0..127
                int c  = (ld & 3) << 2;      // k offset
                float4 v = *reinterpret_cast<const float4*>(
                    &Bb[(size_t)(colBase + r) * K + k0 + c]);
                Bs[c + 0][r] = v.x; Bs[c + 1][r] = v.y;
                Bs[c + 2][r] = v.z; Bs[c + 3][r] = v.w;
            }
        } else {
            #pragma unroll
            for (int i = 0; i < 2; i++) {
                int ld = tid + i * 256;
                int r  = ld >> 5;            // k 0..15
                int c  = (ld & 31) << 2;     // n 0..124
                *reinterpret_cast<float4*>(&Bs[r][c]) =
                    *reinterpret_cast<const float4*>(
                        &Bb[(size_t)(k0 + r) * N + colBase + c]);
            }
        }
        __syncthreads();

        #pragma unroll
        for (int k = 0; k < 16; k++) {
            float4 a0 = *reinterpret_cast<const float4*>(&As[k][ty * 8]);
            float4 a1 = *reinterpret_cast<const float4*>(&As[k][ty * 8 + 4]);
            float4 b0 = *reinterpret_cast<const float4*>(&Bs[k][tx * 8]);
            float4 b1 = *reinterpret_cast<const float4*>(&Bs[k][tx * 8 + 4]);
            float a[8] = {a0.x, a0.y, a0.z, a0.w, a1.x, a1.y, a1.z, a1.w};
            float b[8] = {b0.x, b0.y, b0.z, b0.w, b1.x, b1.y, b1.z, b1.w};
            #pragma unroll
            for (int i = 0; i < 8; i++)
                #pragma unroll
                for (int j = 0; j < 8; j++)
                    acc[i][j] = fmaf(a[i], b[j], acc[i][j]);
        }
        __syncthreads();
    }

    // ---- epilogue ----
    const float* Resb = RES ? (Res + (size_t)bz * sC) : nullptr;
    #pragma unroll
    for (int i = 0; i < 8; i++) {
        int row = rowBase + ty * 8 + i;
        #pragma unroll
        for (int jj = 0; jj < 2; jj++) {
            int col = colBase + tx * 8 + jj * 4;
            float4 v;
            v.x = acc[i][jj * 4 + 0];
            v.y = acc[i][jj * 4 + 1];
            v.z = acc[i][jj * 4 + 2];
            v.w = acc[i][jj * 4 + 3];
            if (BIAS) {
                float4 bb = *reinterpret_cast<const float4*>(&bias[col]);
                v.x += bb.x; v.y += bb.y; v.z += bb.z; v.w += bb.w;
            }
            if (RES) {
                float4 rr = *reinterpret_cast<const float4*>(
                    &Resb[(size_t)row * N + col]);
                v.x += rr.x; v.y += rr.y; v.z += rr.z; v.w += rr.w;
            }
            if (RELU) {
                v.x = fmaxf(v.x, 0.0f); v.y = fmaxf(v.y, 0.0f);
                v.z = fmaxf(v.z, 0.0f); v.w = fmaxf(v.w, 0.0f);
            }
            *reinterpret_cast<float4*>(&Cb[(size_t)row * N + col]) = v;
        }
    }
}

// ---------------------------------------------------------------------------
// Row softmax over rows of length SEQ (2048). One block (256 thr) per row.
// ---------------------------------------------------------------------------
__global__ void __launch_bounds__(256) softmax_k(float* __restrict__ S)
{
    const int row = blockIdx.x;
    float* p = S + (size_t)row * SEQ;
    const int t = threadIdx.x;

    __shared__ float red[256];

    float v[8];
    float m = -1e30f;
    #pragma unroll
    for (int i = 0; i < 8; i++) {
        v[i] = p[t + i * 256];
        m = fmaxf(m, v[i]);
    }
    red[t] = m;
    __syncthreads();
    #pragma unroll
    for (int s = 128; s > 0; s >>= 1) {
        if (t < s) red[t] = fmaxf(red[t], red[t + s]);
        __syncthreads();
    }
    m = red[0];
    __syncthreads();

    float sum = 0.0f;
    #pragma unroll
    for (int i = 0; i < 8; i++) {
        v[i] = expf(v[i] - m);
        sum += v[i];
    }
    red[t] = sum;
    __syncthreads();
    #pragma unroll
    for (int s = 128; s > 0; s >>= 1) {
        if (t < s) red[t] += red[t + s];
        __syncthreads();
    }
    const float inv = 1.0f / red[0];

    #pragma unroll
    for (int i = 0; i < 8; i++)
        p[t + i * 256] = v[i] * inv;
}

// ---------------------------------------------------------------------------
// LayerNorm over rows of length EMBED (1024). One block (256 thr) per row.
// out = (x - mean) * rsqrt(var + 1e-5) * g + b   (biased variance, like jnp.var)
// ---------------------------------------------------------------------------
__global__ void __launch_bounds__(256) layernorm_k(
    const float* __restrict__ in,
    const float* __restrict__ g,
    const float* __restrict__ b,
    float* __restrict__ out)
{
    const int row = blockIdx.x;
    const float* p = in + (size_t)row * EMBED;
    const int t = threadIdx.x;

    __shared__ float r1[256];
    __shared__ float r2[256];

    float4 v = *reinterpret_cast<const float4*>(&p[t * 4]);
    float s  = v.x + v.y + v.z + v.w;
    float sq = v.x * v.x + v.y * v.y + v.z * v.z + v.w * v.w;

    r1[t] = s; r2[t] = sq;
    __syncthreads();
    #pragma unroll
    for (int st = 128; st > 0; st >>= 1) {
        if (t < st) { r1[t] += r1[t + st]; r2[t] += r2[t + st]; }
        __syncthreads();
    }
    const float mean = r1[0] * (1.0f / EMBED);
    const float var  = r2[0] * (1.0f / EMBED) - mean * mean;
    const float rstd = rsqrtf(var + 1e-5f);

    float4 gg = *reinterpret_cast<const float4*>(&g[t * 4]);
    float4 bb = *reinterpret_cast<const float4*>(&b[t * 4]);
    float4 o;
    o.x = (v.x - mean) * rstd * gg.x + bb.x;
    o.y = (v.y - mean) * rstd * gg.y + bb.y;
    o.z = (v.z - mean) * rstd * gg.z + bb.z;
    o.w = (v.w - mean) * rstd * gg.w + bb.w;
    *reinterpret_cast<float4*>(&out[(size_t)row * EMBED + t * 4]) = o;
}

// ---------------------------------------------------------------------------
extern "C" void kernel_launch(void* const* d_in, const int* in_sizes, int n_in,
                              void* d_out, int out_size)
{
    const float* src = (const float*)d_in[0];
    const float* Wq  = (const float*)d_in[1];
    const float* bq  = (const float*)d_in[2];
    const float* Wk  = (const float*)d_in[3];
    const float* bk  = (const float*)d_in[4];
    const float* Wv  = (const float*)d_in[5];
    const float* bv  = (const float*)d_in[6];
    const float* Wo  = (const float*)d_in[7];
    const float* bo  = (const float*)d_in[8];
    const float* W1  = (const float*)d_in[9];
    const float* b1  = (const float*)d_in[10];
    const float* W2  = (const float*)d_in[11];
    const float* b2  = (const float*)d_in[12];
    const float* g1  = (const float*)d_in[13];
    const float* be1 = (const float*)d_in[14];
    const float* g2  = (const float*)d_in[15];
    const float* be2 = (const float*)d_in[16];

    float *Q, *Kp, *V, *SC, *A, *P1, *X, *H, *P2;
    cudaGetSymbolAddress((void**)&Q,  g_Q);
    cudaGetSymbolAddress((void**)&Kp, g_K);
    cudaGetSymbolAddress((void**)&V,  g_V);
    cudaGetSymbolAddress((void**)&SC, g_SC);
    cudaGetSymbolAddress((void**)&A,  g_A);
    cudaGetSymbolAddress((void**)&P1, g_P1);
    cudaGetSymbolAddress((void**)&X,  g_X);
    cudaGetSymbolAddress((void**)&H,  g_H);
    cudaGetSymbolAddress((void**)&P2, g_P2);

    const dim3 blk(256);
    const size_t sQ  = (size_t)SEQ * EMBED;   // per-batch stride, Q/K/V/attn
    const size_t sS  = (size_t)SEQ * SEQ;     // per-batch stride, scores

    // Q/K/V projections: [8192,1024] = src[8192,1024] @ W[1024,1024] + b
    gemm_k<false, true, false, false><<<dim3(EMBED / 128, TOK / 128, 1), blk>>>(
        src, Wq, bq, nullptr, Q, TOK, EMBED, EMBED, 0, 0, 0);
    gemm_k<false, true, false, false><<<dim3(EMBED / 128, TOK / 128, 1), blk>>>(
        src, Wk, bk, nullptr, Kp, TOK, EMBED, EMBED, 0, 0, 0);
    gemm_k<false, true, false, false><<<dim3(EMBED / 128, TOK / 128, 1), blk>>>(
        src, Wv, bv, nullptr, V, TOK, EMBED, EMBED, 0, 0, 0);

    // scores[b] = Q[b] @ K[b]^T  (NT, batched over z)
    gemm_k<true, false, false, false><<<dim3(SEQ / 128, SEQ / 128, BATCH), blk>>>(
        Q, Kp, nullptr, nullptr, SC, SEQ, SEQ, EMBED, sQ, sQ, sS);

    // softmax along rows
    softmax_k<<<BATCH * SEQ, 256>>>(SC);

    // attn[b] = P[b] @ V[b]  (NN, batched)
    gemm_k<false, false, false, false><<<dim3(EMBED / 128, SEQ / 128, BATCH), blk>>>(
        SC, V, nullptr, nullptr, A, SEQ, EMBED, SEQ, sS, sQ, sQ);

    // out-projection + bias + residual(src) -> P1
    gemm_k<false, true, false, true><<<dim3(EMBED / 128, TOK / 128, 1), blk>>>(
        A, Wo, bo, src, P1, TOK, EMBED, EMBED, 0, 0, 0);

    // LN1 -> X
    layernorm_k<<<TOK, 256>>>(P1, g1, be1, X);

    // FFN up: H = relu(X @ W1 + b1)
    gemm_k<false, true, true, false><<<dim3(DFF / 128, TOK / 128, 1), blk>>>(
        X, W1, b1, nullptr, H, TOK, DFF, EMBED, 0, 0, 0);

    // FFN down + bias + residual(X) -> P2
    gemm_k<false, true, false, true><<<dim3(EMBED / 128, TOK / 128, 1), blk>>>(
        H, W2, b2, X, P2, TOK, EMBED, DFF, 0, 0, 0);

    // LN2 -> output
    layernorm_k<<<TOK, 256>>>(P2, g2, be2, (float*)d_out);
}